// round 1
// baseline (speedup 1.0000x reference)
#include <cuda_runtime.h>
#include <math.h>
#include <float.h>

#define NG   32
#define PTS  1024
#define NPT  (NG*PTS)      // 32768
#define KNB  30
#define DIM  64

// ---------------- device scratch (static, no allocations) ----------------
__device__ float g_s[NPT];                       // squared norms
__device__ int   g_idx[NPT*KNB];                 // knn indices (global point ids)
__device__ float g_B[NPT*DIM];                   // x @ W1[F:2F]
__device__ float g_C[NPT*DIM];                   // x @ W1[:F] - B + b1
__device__ float g_hcat[NPT*192];                // [x1 | x2 | x3]
__device__ float g_big[(size_t)NPT*1024];        // distance matrix, later h0
__device__ float g_h1[NPT*256];
__device__ float g_h2[NPT*128];

// ---------------- squared norms ----------------
template<int F>
__global__ void sqnorm_k(const float* __restrict__ x, int ldx) {
    int i = blockIdx.x*256 + threadIdx.x;
    const float* xr = x + (size_t)i*ldx;
    float s = 0.f;
    #pragma unroll
    for (int f = 0; f < F; f++) s += xr[f]*xr[f];
    g_s[i] = s;
}

// ---------------- pairwise distance GEMM: d = s_i + s_j - 2*x_i.x_j ----------------
// per graph, 64x64 output tile per block, 4x4 per thread
template<int F, int BK>
__global__ void dist_k(const float* __restrict__ x, int ldx) {
    __shared__ __align__(16) float As[BK][68];
    __shared__ __align__(16) float Bs[BK][68];
    int g  = blockIdx.z;
    int bm = blockIdx.y*64, bn = blockIdx.x*64;
    int tid = threadIdx.x;
    int tx = tid & 15, ty = tid >> 4;
    const float* xg = x + (size_t)g*PTS*ldx;
    float acc[4][4] = {};
    for (int f0 = 0; f0 < F; f0 += BK) {
        for (int e = tid; e < 64*BK; e += 256) {
            int r = e % BK, c = e / BK;
            As[r][c] = xg[(size_t)(bm + c)*ldx + f0 + r];
            Bs[r][c] = xg[(size_t)(bn + c)*ldx + f0 + r];
        }
        __syncthreads();
        #pragma unroll
        for (int kk = 0; kk < BK; kk++) {
            float a0 = As[kk][ty*4+0], a1 = As[kk][ty*4+1];
            float a2 = As[kk][ty*4+2], a3 = As[kk][ty*4+3];
            float b0 = Bs[kk][tx*4+0], b1 = Bs[kk][tx*4+1];
            float b2 = Bs[kk][tx*4+2], b3 = Bs[kk][tx*4+3];
            acc[0][0]+=a0*b0; acc[0][1]+=a0*b1; acc[0][2]+=a0*b2; acc[0][3]+=a0*b3;
            acc[1][0]+=a1*b0; acc[1][1]+=a1*b1; acc[1][2]+=a1*b2; acc[1][3]+=a1*b3;
            acc[2][0]+=a2*b0; acc[2][1]+=a2*b1; acc[2][2]+=a2*b2; acc[2][3]+=a2*b3;
            acc[3][0]+=a3*b0; acc[3][1]+=a3*b1; acc[3][2]+=a3*b2; acc[3][3]+=a3*b3;
        }
        __syncthreads();
    }
    float sj0 = g_s[g*PTS + bn + tx*4+0];
    float sj1 = g_s[g*PTS + bn + tx*4+1];
    float sj2 = g_s[g*PTS + bn + tx*4+2];
    float sj3 = g_s[g*PTS + bn + tx*4+3];
    #pragma unroll
    for (int u = 0; u < 4; u++) {
        float si = g_s[g*PTS + bm + ty*4 + u];
        float4 o;
        o.x = si + sj0 - 2.f*acc[u][0];
        o.y = si + sj1 - 2.f*acc[u][1];
        o.z = si + sj2 - 2.f*acc[u][2];
        o.w = si + sj3 - 2.f*acc[u][3];
        *(float4*)&g_big[(size_t)(g*PTS + bm + ty*4 + u)*PTS + bn + tx*4] = o;
    }
}

// ---------------- top-K selection (warp per point, register-resident) ----------------
__global__ void topk_k() {
    int w = threadIdx.x >> 5, lane = threadIdx.x & 31;
    int i = blockIdx.x*8 + w;          // global point id
    int g = i >> 10;
    const float* row = &g_big[(size_t)i*PTS];
    float dl[32];
    #pragma unroll
    for (int t = 0; t < 32; t++) dl[t] = row[lane + 32*t];
    float lv = FLT_MAX; int ltt = 0;
    #pragma unroll
    for (int t = 0; t < 32; t++) if (dl[t] < lv) { lv = dl[t]; ltt = t; }
    for (int kk = 0; kk < KNB; kk++) {
        float v = lv; int jv = lane + 32*ltt;
        #pragma unroll
        for (int o = 16; o; o >>= 1) {
            float ov = __shfl_down_sync(0xffffffffu, v,  o);
            int   oj = __shfl_down_sync(0xffffffffu, jv, o);
            if (ov < v || (ov == v && oj < jv)) { v = ov; jv = oj; }
        }
        jv = __shfl_sync(0xffffffffu, jv, 0);
        if (lane == 0) g_idx[(size_t)i*KNB + kk] = (g << 10) + jv;
        if ((jv & 31) == lane) {
            int rt = jv >> 5;
            #pragma unroll
            for (int t = 0; t < 32; t++) if (t == rt) dl[t] = FLT_MAX;
            lv = FLT_MAX; ltt = 0;
            #pragma unroll
            for (int t = 0; t < 32; t++) if (dl[t] < lv) { lv = dl[t]; ltt = t; }
        }
    }
}

// ---------------- precompute B = x@W1_bot, C = x@W1_top - B + b1 ----------------
template<int F>
__global__ void precompute_k(const float* __restrict__ x, int ldx,
                             const float* __restrict__ W1, const float* __restrict__ b1) {
    int gid = blockIdx.x*256 + threadIdx.x;
    int i = gid >> 6, c = gid & 63;
    const float* xr = x + (size_t)i*ldx;
    float a = 0.f, b = 0.f;
    #pragma unroll
    for (int f = 0; f < F; f++) {
        float xv = xr[f];
        a += xv * W1[f*DIM + c];
        b += xv * W1[(F + f)*DIM + c];
    }
    g_B[gid] = b;
    g_C[gid] = a - b + b1[c];
}

// ---------------- edgeconv: out_i = relu( max_k (relu(C_i + B_j) @ W2 + b2) ) ----------------
// 4 points/block, 64 threads/point; 4k x 4c register blocking (0.5 LDS/FFMA)
__global__ void edgeconv_k(const float* __restrict__ W2, const float* __restrict__ b2,
                           float* __restrict__ out, int ldo) {
    __shared__ float sh[4][32][DIM];   // 32 KB (h1, reused for reduction)
    __shared__ float w2s[DIM*DIM];     // 16 KB
    int tid = threadIdx.x;
    #pragma unroll
    for (int t = 0; t < 16; t++) w2s[t*256 + tid] = W2[t*256 + tid];
    int p  = tid >> 6;
    int lt = tid & 63;
    int i  = blockIdx.x*4 + p;
    const int* idxr = g_idx + (size_t)i*KNB;
    float ci = g_C[(size_t)i*DIM + lt];
    #pragma unroll
    for (int k = 0; k < 32; k++) {
        int j = idxr[(k < KNB) ? k : 0];       // pad k=30,31 with a duplicate (max-safe)
        sh[p][k][lt] = fmaxf(ci + g_B[(size_t)j*DIM + lt], 0.f);
    }
    __syncthreads();
    int cg = lt & 15, kg = lt >> 4;
    int c0 = cg, c1 = cg+16, c2 = cg+32, c3 = cg+48;
    float bb0 = b2[c0], bb1 = b2[c1], bb2 = b2[c2], bb3 = b2[c3];
    float mv0 = -FLT_MAX, mv1 = -FLT_MAX, mv2 = -FLT_MAX, mv3 = -FLT_MAX;
    #pragma unroll
    for (int kb = 0; kb < 2; kb++) {
        int k0 = (kg << 3) + (kb << 2);
        float a[4][4];
        #pragma unroll
        for (int q = 0; q < 4; q++) { a[q][0]=bb0; a[q][1]=bb1; a[q][2]=bb2; a[q][3]=bb3; }
        #pragma unroll
        for (int m = 0; m < DIM; m++) {
            float h0 = sh[p][k0+0][m];
            float h1 = sh[p][k0+1][m];
            float h2 = sh[p][k0+2][m];
            float h3 = sh[p][k0+3][m];
            const float* wr = &w2s[m*DIM];
            float w0 = wr[c0], w1 = wr[c1], w2 = wr[c2], w3 = wr[c3];
            a[0][0]+=h0*w0; a[0][1]+=h0*w1; a[0][2]+=h0*w2; a[0][3]+=h0*w3;
            a[1][0]+=h1*w0; a[1][1]+=h1*w1; a[1][2]+=h1*w2; a[1][3]+=h1*w3;
            a[2][0]+=h2*w0; a[2][1]+=h2*w1; a[2][2]+=h2*w2; a[2][3]+=h2*w3;
            a[3][0]+=h3*w0; a[3][1]+=h3*w1; a[3][2]+=h3*w2; a[3][3]+=h3*w3;
        }
        #pragma unroll
        for (int q = 0; q < 4; q++) {
            mv0 = fmaxf(mv0, a[q][0]); mv1 = fmaxf(mv1, a[q][1]);
            mv2 = fmaxf(mv2, a[q][2]); mv3 = fmaxf(mv3, a[q][3]);
        }
    }
    __syncthreads();
    sh[p][kg][c0] = mv0; sh[p][kg][c1] = mv1; sh[p][kg][c2] = mv2; sh[p][kg][c3] = mv3;
    __syncthreads();
    float r = fmaxf(fmaxf(sh[p][0][lt], sh[p][1][lt]),
                    fmaxf(sh[p][2][lt], sh[p][3][lt]));
    out[(size_t)i*ldo + lt] = fmaxf(r, 0.f);
}

// ---------------- generic SGEMM (M x Kd) @ (Kd x Nd) + bias [+relu] ----------------
template<bool RELU>
__global__ void gemm_k(const float* __restrict__ A, const float* __restrict__ Bw,
                       const float* __restrict__ bias, float* __restrict__ C,
                       int Kd, int Nd) {
    __shared__ __align__(16) float As[16][68];
    __shared__ __align__(16) float Bs[16][64];
    int tid = threadIdx.x;
    int tx = tid & 15, ty = tid >> 4;
    int bm = blockIdx.y * 64, bn = blockIdx.x * 64;
    float acc[4][4] = {};
    for (int k0 = 0; k0 < Kd; k0 += 16) {
        #pragma unroll
        for (int q = 0; q < 4; q++) {
            int e = q*256 + tid;
            int r = e & 15, c = e >> 4;
            As[r][c] = A[(size_t)(bm + c)*Kd + k0 + r];
        }
        #pragma unroll
        for (int q = 0; q < 4; q++) {
            int e = q*256 + tid;
            int r = e >> 6, c = e & 63;
            Bs[r][c] = Bw[(size_t)(k0 + r)*Nd + bn + c];
        }
        __syncthreads();
        #pragma unroll
        for (int kk = 0; kk < 16; kk++) {
            float a0 = As[kk][ty*4+0], a1 = As[kk][ty*4+1];
            float a2 = As[kk][ty*4+2], a3 = As[kk][ty*4+3];
            float4 bv = *(const float4*)&Bs[kk][tx*4];
            acc[0][0]+=a0*bv.x; acc[0][1]+=a0*bv.y; acc[0][2]+=a0*bv.z; acc[0][3]+=a0*bv.w;
            acc[1][0]+=a1*bv.x; acc[1][1]+=a1*bv.y; acc[1][2]+=a1*bv.z; acc[1][3]+=a1*bv.w;
            acc[2][0]+=a2*bv.x; acc[2][1]+=a2*bv.y; acc[2][2]+=a2*bv.z; acc[2][3]+=a2*bv.w;
            acc[3][0]+=a3*bv.x; acc[3][1]+=a3*bv.y; acc[3][2]+=a3*bv.z; acc[3][3]+=a3*bv.w;
        }
        __syncthreads();
    }
    float4 bs4 = *(const float4*)&bias[bn + tx*4];
    #pragma unroll
    for (int u = 0; u < 4; u++) {
        float4 o;
        o.x = acc[u][0] + bs4.x; o.y = acc[u][1] + bs4.y;
        o.z = acc[u][2] + bs4.z; o.w = acc[u][3] + bs4.w;
        if (RELU) {
            o.x = fmaxf(o.x, 0.f); o.y = fmaxf(o.y, 0.f);
            o.z = fmaxf(o.z, 0.f); o.w = fmaxf(o.w, 0.f);
        }
        *(float4*)&C[(size_t)(bm + ty*4 + u)*Nd + bn + tx*4] = o;
    }
}

// ---------------- host orchestration ----------------
template<int F, int BK>
static void run_conv(const float* xp, int ldx,
                     const float* w1, const float* b1,
                     const float* w2, const float* b2,
                     float* outp, int ldo) {
    sqnorm_k<F><<<NPT/256, 256>>>(xp, ldx);
    dist_k<F, BK><<<dim3(PTS/64, PTS/64, NG), 256>>>(xp, ldx);
    topk_k<<<NPT/8, 256>>>();
    precompute_k<F><<<(NPT*DIM)/256, 256>>>(xp, ldx, w1, b1);
    edgeconv_k<<<NPT/4, 256>>>(w2, b2, outp, ldo);
}

extern "C" void kernel_launch(void* const* d_in, const int* in_sizes, int n_in,
                              void* d_out, int out_size) {
    const float* x    = (const float*)d_in[0];
    // d_in[1] = batch (implicit: i / 1024), unused
    const float* c1w1 = (const float*)d_in[2];
    const float* c1b1 = (const float*)d_in[3];
    const float* c1w2 = (const float*)d_in[4];
    const float* c1b2 = (const float*)d_in[5];
    const float* c2w1 = (const float*)d_in[6];
    const float* c2b1 = (const float*)d_in[7];
    const float* c2w2 = (const float*)d_in[8];
    const float* c2b2 = (const float*)d_in[9];
    const float* c3w1 = (const float*)d_in[10];
    const float* c3b1 = (const float*)d_in[11];
    const float* c3w2 = (const float*)d_in[12];
    const float* c3b2 = (const float*)d_in[13];
    const float* lw   = (const float*)d_in[14];
    const float* lb   = (const float*)d_in[15];
    const float* hw1  = (const float*)d_in[16];
    const float* hb1  = (const float*)d_in[17];
    const float* hw2  = (const float*)d_in[18];
    const float* hb2  = (const float*)d_in[19];
    const float* hw3  = (const float*)d_in[20];
    const float* hb3  = (const float*)d_in[21];
    float* out = (float*)d_out;

    float *hcat, *big, *h1b, *h2b;
    cudaGetSymbolAddress((void**)&hcat, g_hcat);
    cudaGetSymbolAddress((void**)&big,  g_big);
    cudaGetSymbolAddress((void**)&h1b,  g_h1);
    cudaGetSymbolAddress((void**)&h2b,  g_h2);

    run_conv<14, 14>(x,        14,  c1w1, c1b1, c1w2, c1b2, hcat,       192);
    run_conv<64, 16>(hcat,     192, c2w1, c2b1, c2w2, c2b2, hcat + 64,  192);
    run_conv<64, 16>(hcat + 64,192, c3w1, c3b1, c3w2, c3b2, hcat + 128, 192);

    gemm_k<true ><<<dim3(16, 512), 256>>>(hcat, lw,  lb,  big,  192,  1024);
    gemm_k<true ><<<dim3(4,  512), 256>>>(big,  hw1, hb1, h1b,  1024, 256);
    gemm_k<true ><<<dim3(2,  512), 256>>>(h1b,  hw2, hb2, h2b,  256,  128);
    gemm_k<false><<<dim3(1,  512), 256>>>(h2b,  hw3, hb3, out,  128,  64);
}

// round 2
// speedup vs baseline: 1.1676x; 1.1676x over previous
#include <cuda_runtime.h>
#include <math.h>
#include <float.h>

#define NG   32
#define PTS  1024
#define NPT  (NG*PTS)      // 32768
#define KNB  30
#define DIM  64

// ---------------- device scratch (static, no allocations) ----------------
__device__ float g_s[NPT];                       // squared norms
__device__ int   g_idx[NPT*KNB];                 // knn indices (global point ids)
__device__ float g_B[NPT*DIM];                   // x @ W1[F:2F]
__device__ float g_C[NPT*DIM];                   // x @ W1[:F] - B + b1
__device__ float g_hcat[NPT*192];                // [x1 | x2 | x3]
__device__ float g_big[(size_t)NPT*1024];        // distance matrix, later h0
__device__ float g_h1[NPT*256];
__device__ float g_h2[NPT*128];

__device__ __forceinline__ unsigned tf32u(float x) {
    unsigned u;
    asm("cvt.rna.tf32.f32 %0, %1;" : "=r"(u) : "f"(x));
    return u;
}

// ---------------- squared norms ----------------
template<int F>
__global__ void sqnorm_k(const float* __restrict__ x, int ldx) {
    int i = blockIdx.x*256 + threadIdx.x;
    const float* xr = x + (size_t)i*ldx;
    float s = 0.f;
    #pragma unroll
    for (int f = 0; f < F; f++) s += xr[f]*xr[f];
    g_s[i] = s;
}

// ---------------- pairwise distance GEMM: d = s_i + s_j - 2*x_i.x_j ----------------
template<int F, int BK>
__global__ void dist_k(const float* __restrict__ x, int ldx) {
    __shared__ __align__(16) float As[BK][68];
    __shared__ __align__(16) float Bs[BK][68];
    int g  = blockIdx.z;
    int bm = blockIdx.y*64, bn = blockIdx.x*64;
    int tid = threadIdx.x;
    int tx = tid & 15, ty = tid >> 4;
    const float* xg = x + (size_t)g*PTS*ldx;
    float acc[4][4] = {};
    for (int f0 = 0; f0 < F; f0 += BK) {
        for (int e = tid; e < 64*BK; e += 256) {
            int r = e % BK, c = e / BK;
            As[r][c] = xg[(size_t)(bm + c)*ldx + f0 + r];
            Bs[r][c] = xg[(size_t)(bn + c)*ldx + f0 + r];
        }
        __syncthreads();
        #pragma unroll
        for (int kk = 0; kk < BK; kk++) {
            float a0 = As[kk][ty*4+0], a1 = As[kk][ty*4+1];
            float a2 = As[kk][ty*4+2], a3 = As[kk][ty*4+3];
            float b0 = Bs[kk][tx*4+0], b1 = Bs[kk][tx*4+1];
            float b2 = Bs[kk][tx*4+2], b3 = Bs[kk][tx*4+3];
            acc[0][0]+=a0*b0; acc[0][1]+=a0*b1; acc[0][2]+=a0*b2; acc[0][3]+=a0*b3;
            acc[1][0]+=a1*b0; acc[1][1]+=a1*b1; acc[1][2]+=a1*b2; acc[1][3]+=a1*b3;
            acc[2][0]+=a2*b0; acc[2][1]+=a2*b1; acc[2][2]+=a2*b2; acc[2][3]+=a2*b3;
            acc[3][0]+=a3*b0; acc[3][1]+=a3*b1; acc[3][2]+=a3*b2; acc[3][3]+=a3*b3;
        }
        __syncthreads();
    }
    float sj0 = g_s[g*PTS + bn + tx*4+0];
    float sj1 = g_s[g*PTS + bn + tx*4+1];
    float sj2 = g_s[g*PTS + bn + tx*4+2];
    float sj3 = g_s[g*PTS + bn + tx*4+3];
    #pragma unroll
    for (int u = 0; u < 4; u++) {
        float si = g_s[g*PTS + bm + ty*4 + u];
        float4 o;
        o.x = si + sj0 - 2.f*acc[u][0];
        o.y = si + sj1 - 2.f*acc[u][1];
        o.z = si + sj2 - 2.f*acc[u][2];
        o.w = si + sj3 - 2.f*acc[u][3];
        *(float4*)&g_big[(size_t)(g*PTS + bm + ty*4 + u)*PTS + bn + tx*4] = o;
    }
}

// ---------------- top-K selection (warp per point, register-resident) ----------------
__global__ void topk_k() {
    int w = threadIdx.x >> 5, lane = threadIdx.x & 31;
    int i = blockIdx.x*8 + w;          // global point id
    int g = i >> 10;
    const float* row = &g_big[(size_t)i*PTS];
    float dl[32];
    #pragma unroll
    for (int t = 0; t < 32; t++) dl[t] = row[lane + 32*t];
    float lv = FLT_MAX; int ltt = 0;
    #pragma unroll
    for (int t = 0; t < 32; t++) if (dl[t] < lv) { lv = dl[t]; ltt = t; }
    for (int kk = 0; kk < KNB; kk++) {
        float v = lv; int jv = lane + 32*ltt;
        #pragma unroll
        for (int o = 16; o; o >>= 1) {
            float ov = __shfl_down_sync(0xffffffffu, v,  o);
            int   oj = __shfl_down_sync(0xffffffffu, jv, o);
            if (ov < v || (ov == v && oj < jv)) { v = ov; jv = oj; }
        }
        jv = __shfl_sync(0xffffffffu, jv, 0);
        if (lane == 0) g_idx[(size_t)i*KNB + kk] = (g << 10) + jv;
        if ((jv & 31) == lane) {
            int rt = jv >> 5;
            #pragma unroll
            for (int t = 0; t < 32; t++) if (t == rt) dl[t] = FLT_MAX;
            lv = FLT_MAX; ltt = 0;
            #pragma unroll
            for (int t = 0; t < 32; t++) if (dl[t] < lv) { lv = dl[t]; ltt = t; }
        }
    }
}

// ---------------- precompute B = x@W1_bot, C = x@W1_top - B + b1 ----------------
template<int F>
__global__ void precompute_k(const float* __restrict__ x, int ldx,
                             const float* __restrict__ W1, const float* __restrict__ b1) {
    int gid = blockIdx.x*256 + threadIdx.x;
    int i = gid >> 6, c = gid & 63;
    const float* xr = x + (size_t)i*ldx;
    float a = 0.f, b = 0.f;
    #pragma unroll
    for (int f = 0; f < F; f++) {
        float xv = xr[f];
        a += xv * W1[f*DIM + c];
        b += xv * W1[(F + f)*DIM + c];
    }
    g_B[gid] = b;
    g_C[gid] = a - b + b1[c];
}

// ---------------- edgeconv: out_i = relu( max_k (relu(C_i + B_j) @ W2 + b2) ) ----------------
// 2 points/block, 64 threads/point; sh transposed [feat][k] (stride 34) so the
// inner loop reads h via 2 broadcast float2s + 1 conflict-free float4 weight read.
__global__ void __launch_bounds__(128) edgeconv_k(
        const float* __restrict__ W2, const float* __restrict__ b2,
        float* __restrict__ out, int ldo) {
    __shared__ float sh[2*64*34];      // [p][f][k] (k stride 1, f stride 34)
    __shared__ float w2s[64*64];
    int tid = threadIdx.x;             // 128 threads
    #pragma unroll
    for (int t = 0; t < 32; t++) w2s[t*128 + tid] = W2[t*128 + tid];
    int p  = tid >> 6;
    int lt = tid & 63;
    int i  = blockIdx.x*2 + p;
    const int* idxr = g_idx + (size_t)i*KNB;
    float ci = g_C[(size_t)i*DIM + lt];
    float* shp = sh + p*64*34;
    #pragma unroll
    for (int k = 0; k < 32; k++) {
        int j = idxr[(k < KNB) ? k : 0];       // pad (max-safe duplicate)
        shp[lt*34 + k] = fmaxf(ci + g_B[(size_t)j*DIM + lt], 0.f);
    }
    __syncthreads();
    int cg = lt & 15, kg = lt >> 4;            // kg in 0..3 -> neighbors kg*8..+7
    int c0 = cg*4;
    float4 bb = *(const float4*)&b2[c0];
    float mv0=-FLT_MAX, mv1=-FLT_MAX, mv2=-FLT_MAX, mv3=-FLT_MAX;
    #pragma unroll
    for (int kb = 0; kb < 2; kb++) {
        int k0 = kg*8 + kb*4;
        float a[4][4];
        #pragma unroll
        for (int q = 0; q < 4; q++) { a[q][0]=bb.x; a[q][1]=bb.y; a[q][2]=bb.z; a[q][3]=bb.w; }
        #pragma unroll 8
        for (int m = 0; m < DIM; m++) {
            float2 h01 = *(const float2*)&shp[m*34 + k0];
            float2 h23 = *(const float2*)&shp[m*34 + k0 + 2];
            float4 w   = *(const float4*)&w2s[m*64 + c0];
            a[0][0]+=h01.x*w.x; a[0][1]+=h01.x*w.y; a[0][2]+=h01.x*w.z; a[0][3]+=h01.x*w.w;
            a[1][0]+=h01.y*w.x; a[1][1]+=h01.y*w.y; a[1][2]+=h01.y*w.z; a[1][3]+=h01.y*w.w;
            a[2][0]+=h23.x*w.x; a[2][1]+=h23.x*w.y; a[2][2]+=h23.x*w.z; a[2][3]+=h23.x*w.w;
            a[3][0]+=h23.y*w.x; a[3][1]+=h23.y*w.y; a[3][2]+=h23.y*w.z; a[3][3]+=h23.y*w.w;
        }
        #pragma unroll
        for (int q = 0; q < 4; q++) {
            mv0 = fmaxf(mv0, a[q][0]); mv1 = fmaxf(mv1, a[q][1]);
            mv2 = fmaxf(mv2, a[q][2]); mv3 = fmaxf(mv3, a[q][3]);
        }
    }
    __syncthreads();
    float* red = sh + p*64*34;   // reuse (safe after barrier)
    red[kg*64 + c0+0] = mv0;
    red[kg*64 + c0+1] = mv1;
    red[kg*64 + c0+2] = mv2;
    red[kg*64 + c0+3] = mv3;
    __syncthreads();
    float r = fmaxf(fmaxf(red[lt], red[64+lt]), fmaxf(red[128+lt], red[192+lt]));
    out[(size_t)i*ldo + lt] = fmaxf(r, 0.f);
}

// ---------------- 3xTF32 tensor-core GEMM + bias [+relu] ----------------
// Block 128(M) x 64(N), K-tile 32, 256 threads (warps 4M x 2N), warp tile 32x32.
// Accuracy: hi/lo split (hi*hi + hi*lo + lo*hi) -> ~2^-22 relative, fp32-like.
#define MMA_TF32(d, a0,a1,a2,a3, b0,b1) \
    asm volatile("mma.sync.aligned.m16n8k8.row.col.f32.tf32.tf32.f32 " \
        "{%0,%1,%2,%3}, {%4,%5,%6,%7}, {%8,%9}, {%0,%1,%2,%3};" \
        : "+f"(d[0]),"+f"(d[1]),"+f"(d[2]),"+f"(d[3]) \
        : "r"(a0),"r"(a1),"r"(a2),"r"(a3), "r"(b0),"r"(b1))

template<bool RELU>
__global__ void __launch_bounds__(256, 2) tgemm_k(
        const float* __restrict__ A, const float* __restrict__ Bw,
        const float* __restrict__ bias, float* __restrict__ C,
        int Kd, int Nd) {
    __shared__ __align__(16) float As[128*36];    // raw fp32, [m][k] stride 36
    __shared__ __align__(16) float Bh[32*72];     // tf32-hi bits, [k][n] stride 72
    __shared__ __align__(16) float Bl[32*72];     // tf32-lo bits
    int tid  = threadIdx.x;
    int lane = tid & 31, warp = tid >> 5;
    int wm = warp & 3, wn = warp >> 2;
    int lr = lane >> 2, lc = lane & 3;
    int bm = blockIdx.y * 128, bn = blockIdx.x * 64;
    float acc[2][4][4];
    #pragma unroll
    for (int mi = 0; mi < 2; mi++)
        #pragma unroll
        for (int ni = 0; ni < 4; ni++)
            #pragma unroll
            for (int q = 0; q < 4; q++) acc[mi][ni][q] = 0.f;

    for (int k0 = 0; k0 < Kd; k0 += 32) {
        float4 av[4], bv[2];
        #pragma unroll
        for (int q = 0; q < 4; q++) {
            int e = q*256 + tid;
            int r = e >> 3, kq = (e & 7) << 2;
            av[q] = *(const float4*)&A[(size_t)(bm + r)*Kd + k0 + kq];
        }
        #pragma unroll
        for (int q = 0; q < 2; q++) {
            int e = q*256 + tid;
            int r = e >> 4, nq = (e & 15) << 2;
            bv[q] = *(const float4*)&Bw[(size_t)(k0 + r)*Nd + bn + nq];
        }
        __syncthreads();
        #pragma unroll
        for (int q = 0; q < 4; q++) {
            int e = q*256 + tid;
            int r = e >> 3, kq = (e & 7) << 2;
            *(float4*)&As[r*36 + kq] = av[q];
        }
        #pragma unroll
        for (int q = 0; q < 2; q++) {
            int e = q*256 + tid;
            int r = e >> 4, nq = (e & 15) << 2;
            unsigned h0 = tf32u(bv[q].x), h1 = tf32u(bv[q].y);
            unsigned h2 = tf32u(bv[q].z), h3 = tf32u(bv[q].w);
            float4 hv = make_float4(__uint_as_float(h0), __uint_as_float(h1),
                                    __uint_as_float(h2), __uint_as_float(h3));
            float4 lv = make_float4(
                __uint_as_float(tf32u(bv[q].x - __uint_as_float(h0))),
                __uint_as_float(tf32u(bv[q].y - __uint_as_float(h1))),
                __uint_as_float(tf32u(bv[q].z - __uint_as_float(h2))),
                __uint_as_float(tf32u(bv[q].w - __uint_as_float(h3))));
            *(float4*)&Bh[r*72 + nq] = hv;
            *(float4*)&Bl[r*72 + nq] = lv;
        }
        __syncthreads();
        #pragma unroll
        for (int ks = 0; ks < 4; ks++) {
            int k8 = ks*8;
            unsigned ah[2][4], al[2][4];
            #pragma unroll
            for (int mi = 0; mi < 2; mi++) {
                int rb = wm*32 + mi*16 + lr;
                float v0 = As[rb*36     + k8 + lc];
                float v1 = As[(rb+8)*36 + k8 + lc];
                float v2 = As[rb*36     + k8 + lc + 4];
                float v3 = As[(rb+8)*36 + k8 + lc + 4];
                ah[mi][0] = tf32u(v0); al[mi][0] = tf32u(v0 - __uint_as_float(ah[mi][0]));
                ah[mi][1] = tf32u(v1); al[mi][1] = tf32u(v1 - __uint_as_float(ah[mi][1]));
                ah[mi][2] = tf32u(v2); al[mi][2] = tf32u(v2 - __uint_as_float(ah[mi][2]));
                ah[mi][3] = tf32u(v3); al[mi][3] = tf32u(v3 - __uint_as_float(ah[mi][3]));
            }
            #pragma unroll
            for (int ni = 0; ni < 4; ni++) {
                int nb = wn*32 + ni*8 + lr;
                unsigned bh0 = __float_as_uint(Bh[(k8 + lc)*72     + nb]);
                unsigned bh1 = __float_as_uint(Bh[(k8 + lc + 4)*72 + nb]);
                unsigned bl0 = __float_as_uint(Bl[(k8 + lc)*72     + nb]);
                unsigned bl1 = __float_as_uint(Bl[(k8 + lc + 4)*72 + nb]);
                #pragma unroll
                for (int mi = 0; mi < 2; mi++) {
                    MMA_TF32(acc[mi][ni], ah[mi][0],ah[mi][1],ah[mi][2],ah[mi][3], bh0,bh1);
                    MMA_TF32(acc[mi][ni], ah[mi][0],ah[mi][1],ah[mi][2],ah[mi][3], bl0,bl1);
                    MMA_TF32(acc[mi][ni], al[mi][0],al[mi][1],al[mi][2],al[mi][3], bh0,bh1);
                }
            }
        }
        __syncthreads();
    }
    #pragma unroll
    for (int mi = 0; mi < 2; mi++) {
        int row = bm + wm*32 + mi*16 + lr;
        #pragma unroll
        for (int ni = 0; ni < 4; ni++) {
            int col = bn + wn*32 + ni*8 + 2*lc;
            float bz0 = bias[col], bz1 = bias[col+1];
            float z0 = acc[mi][ni][0] + bz0;
            float z1 = acc[mi][ni][1] + bz1;
            float z2 = acc[mi][ni][2] + bz0;
            float z3 = acc[mi][ni][3] + bz1;
            if (RELU) {
                z0 = fmaxf(z0, 0.f); z1 = fmaxf(z1, 0.f);
                z2 = fmaxf(z2, 0.f); z3 = fmaxf(z3, 0.f);
            }
            float2 o0 = make_float2(z0, z1);
            float2 o1 = make_float2(z2, z3);
            *(float2*)&C[(size_t)row*Nd + col]     = o0;
            *(float2*)&C[(size_t)(row+8)*Nd + col] = o1;
        }
    }
}

// ---------------- host orchestration ----------------
template<int F, int BK>
static void run_conv(const float* xp, int ldx,
                     const float* w1, const float* b1,
                     const float* w2, const float* b2,
                     float* outp, int ldo) {
    sqnorm_k<F><<<NPT/256, 256>>>(xp, ldx);
    dist_k<F, BK><<<dim3(PTS/64, PTS/64, NG), 256>>>(xp, ldx);
    topk_k<<<NPT/8, 256>>>();
    precompute_k<F><<<(NPT*DIM)/256, 256>>>(xp, ldx, w1, b1);
    edgeconv_k<<<NPT/2, 128>>>(w2, b2, outp, ldo);
}

extern "C" void kernel_launch(void* const* d_in, const int* in_sizes, int n_in,
                              void* d_out, int out_size) {
    const float* x    = (const float*)d_in[0];
    const float* c1w1 = (const float*)d_in[2];
    const float* c1b1 = (const float*)d_in[3];
    const float* c1w2 = (const float*)d_in[4];
    const float* c1b2 = (const float*)d_in[5];
    const float* c2w1 = (const float*)d_in[6];
    const float* c2b1 = (const float*)d_in[7];
    const float* c2w2 = (const float*)d_in[8];
    const float* c2b2 = (const float*)d_in[9];
    const float* c3w1 = (const float*)d_in[10];
    const float* c3b1 = (const float*)d_in[11];
    const float* c3w2 = (const float*)d_in[12];
    const float* c3b2 = (const float*)d_in[13];
    const float* lw   = (const float*)d_in[14];
    const float* lb   = (const float*)d_in[15];
    const float* hw1  = (const float*)d_in[16];
    const float* hb1  = (const float*)d_in[17];
    const float* hw2  = (const float*)d_in[18];
    const float* hb2  = (const float*)d_in[19];
    const float* hw3  = (const float*)d_in[20];
    const float* hb3  = (const float*)d_in[21];
    float* out = (float*)d_out;

    float *hcat, *big, *h1b, *h2b;
    cudaGetSymbolAddress((void**)&hcat, g_hcat);
    cudaGetSymbolAddress((void**)&big,  g_big);
    cudaGetSymbolAddress((void**)&h1b,  g_h1);
    cudaGetSymbolAddress((void**)&h2b,  g_h2);

    run_conv<14, 14>(x,        14,  c1w1, c1b1, c1w2, c1b2, hcat,       192);
    run_conv<64, 16>(hcat,     192, c2w1, c2b1, c2w2, c2b2, hcat + 64,  192);
    run_conv<64, 16>(hcat + 64,192, c3w1, c3b1, c3w2, c3b2, hcat + 128, 192);

    tgemm_k<true ><<<dim3(16, 256), 256>>>(hcat, lw,  lb,  big, 192,  1024);
    tgemm_k<true ><<<dim3(4,  256), 256>>>(big,  hw1, hb1, h1b, 1024, 256);
    tgemm_k<true ><<<dim3(2,  256), 256>>>(h1b,  hw2, hb2, h2b, 256,  128);
    tgemm_k<false><<<dim3(1,  256), 256>>>(h2b,  hw3, hb3, out, 128,  64);
}

// round 3
// speedup vs baseline: 1.3689x; 1.1724x over previous
#include <cuda_runtime.h>
#include <math.h>
#include <float.h>

#define NG   32
#define PTS  1024
#define NPT  (NG*PTS)      // 32768
#define KNB  30
#define DIM  64

// ---------------- device scratch (static, no allocations) ----------------
__device__ float g_s[NPT];                       // squared norms
__device__ int   g_idx[NPT*KNB];                 // knn indices (global point ids)
__device__ float g_B[NPT*DIM];                   // x @ W1[F:2F]
__device__ float g_C[NPT*DIM];                   // x @ W1[:F] - B + b1
__device__ float g_hcat[NPT*192];                // [x1 | x2 | x3]
__device__ float g_big[(size_t)NPT*1024];        // distance matrix, later h0
__device__ float g_h1[NPT*256];
__device__ float g_h2[NPT*128];
__device__ unsigned g_w2h[64*32];                // W2 split hi, [n][pair]
__device__ unsigned g_w2l[64*32];                // W2 split lo

// ---------------- bf16 split helpers ----------------
__device__ __forceinline__ unsigned packbf(float lo, float hi) {
    unsigned r;
    asm("cvt.rn.bf16x2.f32 %0, %1, %2;" : "=r"(r) : "f"(hi), "f"(lo));
    return r;
}
// split (x,y) into packed bf16 hi pair + packed bf16 residual pair
__device__ __forceinline__ void split2(float x, float y, unsigned& h, unsigned& l) {
    h = packbf(x, y);
    float hx = __uint_as_float(h << 16);
    float hy = __uint_as_float(h & 0xffff0000u);
    l = packbf(x - hx, y - hy);
}

#define MMA_BF16(d, a0,a1,a2,a3, b0,b1) \
    asm volatile("mma.sync.aligned.m16n8k16.row.col.f32.bf16.bf16.f32 " \
        "{%0,%1,%2,%3}, {%4,%5,%6,%7}, {%8,%9}, {%0,%1,%2,%3};" \
        : "+f"(d[0]),"+f"(d[1]),"+f"(d[2]),"+f"(d[3]) \
        : "r"(a0),"r"(a1),"r"(a2),"r"(a3), "r"(b0),"r"(b1))

// ---------------- squared norms ----------------
template<int F>
__global__ void sqnorm_k(const float* __restrict__ x, int ldx) {
    int i = blockIdx.x*256 + threadIdx.x;
    const float* xr = x + (size_t)i*ldx;
    float s = 0.f;
    #pragma unroll
    for (int f = 0; f < F; f++) s += xr[f]*xr[f];
    g_s[i] = s;
}

// ---------------- pairwise distance GEMM: d = s_i + s_j - 2*x_i.x_j ----------------
template<int F, int BK>
__global__ void dist_k(const float* __restrict__ x, int ldx) {
    __shared__ __align__(16) float As[BK][68];
    __shared__ __align__(16) float Bs[BK][68];
    int g  = blockIdx.z;
    int bm = blockIdx.y*64, bn = blockIdx.x*64;
    int tid = threadIdx.x;
    int tx = tid & 15, ty = tid >> 4;
    const float* xg = x + (size_t)g*PTS*ldx;
    float acc[4][4] = {};
    for (int f0 = 0; f0 < F; f0 += BK) {
        for (int e = tid; e < 64*BK; e += 256) {
            int r = e % BK, c = e / BK;
            As[r][c] = xg[(size_t)(bm + c)*ldx + f0 + r];
            Bs[r][c] = xg[(size_t)(bn + c)*ldx + f0 + r];
        }
        __syncthreads();
        #pragma unroll
        for (int kk = 0; kk < BK; kk++) {
            float a0 = As[kk][ty*4+0], a1 = As[kk][ty*4+1];
            float a2 = As[kk][ty*4+2], a3 = As[kk][ty*4+3];
            float b0 = Bs[kk][tx*4+0], b1 = Bs[kk][tx*4+1];
            float b2 = Bs[kk][tx*4+2], b3 = Bs[kk][tx*4+3];
            acc[0][0]+=a0*b0; acc[0][1]+=a0*b1; acc[0][2]+=a0*b2; acc[0][3]+=a0*b3;
            acc[1][0]+=a1*b0; acc[1][1]+=a1*b1; acc[1][2]+=a1*b2; acc[1][3]+=a1*b3;
            acc[2][0]+=a2*b0; acc[2][1]+=a2*b1; acc[2][2]+=a2*b2; acc[2][3]+=a2*b3;
            acc[3][0]+=a3*b0; acc[3][1]+=a3*b1; acc[3][2]+=a3*b2; acc[3][3]+=a3*b3;
        }
        __syncthreads();
    }
    float sj0 = g_s[g*PTS + bn + tx*4+0];
    float sj1 = g_s[g*PTS + bn + tx*4+1];
    float sj2 = g_s[g*PTS + bn + tx*4+2];
    float sj3 = g_s[g*PTS + bn + tx*4+3];
    #pragma unroll
    for (int u = 0; u < 4; u++) {
        float si = g_s[g*PTS + bm + ty*4 + u];
        float4 o;
        o.x = si + sj0 - 2.f*acc[u][0];
        o.y = si + sj1 - 2.f*acc[u][1];
        o.z = si + sj2 - 2.f*acc[u][2];
        o.w = si + sj3 - 2.f*acc[u][3];
        *(float4*)&g_big[(size_t)(g*PTS + bm + ty*4 + u)*PTS + bn + tx*4] = o;
    }
}

// ---------------- top-K selection (warp per point, register-resident) ----------------
__global__ void topk_k() {
    int w = threadIdx.x >> 5, lane = threadIdx.x & 31;
    int i = blockIdx.x*8 + w;
    int g = i >> 10;
    const float* row = &g_big[(size_t)i*PTS];
    float dl[32];
    #pragma unroll
    for (int t = 0; t < 32; t++) dl[t] = row[lane + 32*t];
    float lv = FLT_MAX; int ltt = 0;
    #pragma unroll
    for (int t = 0; t < 32; t++) if (dl[t] < lv) { lv = dl[t]; ltt = t; }
    for (int kk = 0; kk < KNB; kk++) {
        float v = lv; int jv = lane + 32*ltt;
        #pragma unroll
        for (int o = 16; o; o >>= 1) {
            float ov = __shfl_down_sync(0xffffffffu, v,  o);
            int   oj = __shfl_down_sync(0xffffffffu, jv, o);
            if (ov < v || (ov == v && oj < jv)) { v = ov; jv = oj; }
        }
        jv = __shfl_sync(0xffffffffu, jv, 0);
        if (lane == 0) g_idx[(size_t)i*KNB + kk] = (g << 10) + jv;
        if ((jv & 31) == lane) {
            int rt = jv >> 5;
            #pragma unroll
            for (int t = 0; t < 32; t++) if (t == rt) dl[t] = FLT_MAX;
            lv = FLT_MAX; ltt = 0;
            #pragma unroll
            for (int t = 0; t < 32; t++) if (dl[t] < lv) { lv = dl[t]; ltt = t; }
        }
    }
}

// ---------------- precompute B = x@W1_bot, C = x@W1_top - B + b1 ----------------
template<int F>
__global__ void precompute_k(const float* __restrict__ x, int ldx,
                             const float* __restrict__ W1, const float* __restrict__ b1) {
    int gid = blockIdx.x*256 + threadIdx.x;
    int i = gid >> 6, c = gid & 63;
    const float* xr = x + (size_t)i*ldx;
    float a = 0.f, b = 0.f;
    #pragma unroll
    for (int f = 0; f < F; f++) {
        float xv = xr[f];
        a += xv * W1[f*DIM + c];
        b += xv * W1[(F + f)*DIM + c];
    }
    g_B[gid] = b;
    g_C[gid] = a - b + b1[c];
}

// ---------------- W2 -> packed bf16 hi/lo [n][pair] in global ----------------
__global__ void w2prep_k(const float* __restrict__ W2) {
    int e = blockIdx.x*256 + threadIdx.x;   // 2048 entries
    int n = e & 63, j = e >> 6;             // j = feature pair 0..31
    float w0 = W2[(2*j)*64 + n];
    float w1 = W2[(2*j+1)*64 + n];
    unsigned h, l; split2(w0, w1, h, l);
    g_w2h[n*32 + j] = h;
    g_w2l[n*32 + j] = l;
}

// ---------------- edgeconv via bf16 tensor cores ----------------
// out_i = relu( max_k (relu(C_i + B_j) @ W2) + b2 )
// 1 warp per point; h staged as packed bf16 hi/lo pairs [k][pair] stride 36
// (conflict-free frag reads); W2 frags read from L1-resident global splits.
__global__ void __launch_bounds__(128) edgeconv_k(
        const float* __restrict__ b2, float* __restrict__ out, int ldo) {
    __shared__ unsigned Hh[4][32][36];
    __shared__ unsigned Hl[4][32][36];
    int tid = threadIdx.x, lane = tid & 31, warp = tid >> 5;
    int gid = lane >> 2, tig = lane & 3;
    int i = blockIdx.x*4 + warp;

    // stage h = relu(C_i + B_j) for 32 neighbor slots (pad >=30 with dup of 0)
    unsigned (*hh)[36] = Hh[warp];
    unsigned (*hl)[36] = Hl[warp];
    const int* idxr = g_idx + (size_t)i*KNB;
    float2 cv = *(const float2*)&g_C[(size_t)i*DIM + 2*lane];
    #pragma unroll
    for (int k = 0; k < 32; k++) {
        int j = idxr[(k < KNB) ? k : 0];
        float2 bv = *(const float2*)&g_B[(size_t)j*DIM + 2*lane];
        float f0 = fmaxf(cv.x + bv.x, 0.f);
        float f1 = fmaxf(cv.y + bv.y, 0.f);
        unsigned h, l; split2(f0, f1, h, l);
        hh[k][lane] = h;
        hl[k][lane] = l;
    }
    __syncwarp();

    float acc[2][8][4] = {};
    #pragma unroll
    for (int s = 0; s < 4; s++) {           // K = 64 -> 4 k16-steps
        int p = s*8 + tig;
        unsigned ah[2][4], al[2][4];
        #pragma unroll
        for (int mi = 0; mi < 2; mi++) {
            int r = mi*16 + gid;
            ah[mi][0] = hh[r][p];   ah[mi][1] = hh[r+8][p];
            ah[mi][2] = hh[r][p+4]; ah[mi][3] = hh[r+8][p+4];
            al[mi][0] = hl[r][p];   al[mi][1] = hl[r+8][p];
            al[mi][2] = hl[r][p+4]; al[mi][3] = hl[r+8][p+4];
        }
        #pragma unroll
        for (int ni = 0; ni < 8; ni++) {
            int c = ni*8 + gid;
            unsigned bh0 = g_w2h[c*32 + p], bh1 = g_w2h[c*32 + p + 4];
            unsigned bl0 = g_w2l[c*32 + p], bl1 = g_w2l[c*32 + p + 4];
            #pragma unroll
            for (int mi = 0; mi < 2; mi++) {
                MMA_BF16(acc[mi][ni], ah[mi][0],ah[mi][1],ah[mi][2],ah[mi][3], bh0,bh1);
                MMA_BF16(acc[mi][ni], ah[mi][0],ah[mi][1],ah[mi][2],ah[mi][3], bl0,bl1);
                MMA_BF16(acc[mi][ni], al[mi][0],al[mi][1],al[mi][2],al[mi][3], bh0,bh1);
            }
        }
    }
    // max over neighbors (rows): in-thread over 4 row slots, then shfl over gid
    #pragma unroll
    for (int ni = 0; ni < 8; ni++) {
        float m0 = fmaxf(fmaxf(acc[0][ni][0], acc[0][ni][2]),
                         fmaxf(acc[1][ni][0], acc[1][ni][2]));
        float m1 = fmaxf(fmaxf(acc[0][ni][1], acc[0][ni][3]),
                         fmaxf(acc[1][ni][1], acc[1][ni][3]));
        m0 = fmaxf(m0, __shfl_xor_sync(0xffffffffu, m0, 4));
        m1 = fmaxf(m1, __shfl_xor_sync(0xffffffffu, m1, 4));
        m0 = fmaxf(m0, __shfl_xor_sync(0xffffffffu, m0, 8));
        m1 = fmaxf(m1, __shfl_xor_sync(0xffffffffu, m1, 8));
        m0 = fmaxf(m0, __shfl_xor_sync(0xffffffffu, m0, 16));
        m1 = fmaxf(m1, __shfl_xor_sync(0xffffffffu, m1, 16));
        if (gid == 0) {
            int col = ni*8 + tig*2;
            float2 bz = *(const float2*)&b2[col];
            float2 o;
            o.x = fmaxf(m0 + bz.x, 0.f);
            o.y = fmaxf(m1 + bz.y, 0.f);
            *(float2*)&out[(size_t)i*ldo + col] = o;
        }
    }
}

// ---------------- 3-term bf16-split tensor-core GEMM + bias [+relu] ----------------
// Block 128(M) x 64(N), K-tile 32, 256 threads, warps 4M x 2N, warp tile 32x32.
template<bool RELU>
__global__ void __launch_bounds__(256, 2) hgemm_k(
        const float* __restrict__ A, const float* __restrict__ Bw,
        const float* __restrict__ bias, float* __restrict__ C,
        int Kd, int Nd) {
    __shared__ unsigned Ah[128][17], Al[128][17];   // [m][pair 0..15]
    __shared__ unsigned Bh[64][17],  Bl[64][17];    // [n][pair 0..15]
    int tid  = threadIdx.x;
    int lane = tid & 31, warp = tid >> 5;
    int wm = warp & 3, wn = warp >> 2;
    int gid = lane >> 2, tig = lane & 3;
    int bm = blockIdx.y * 128, bn = blockIdx.x * 64;
    float acc[2][4][4] = {};

    for (int k0 = 0; k0 < Kd; k0 += 32) {
        float4 av[4]; float bv0[4], bv1[4];
        #pragma unroll
        for (int q = 0; q < 4; q++) {
            int e = q*256 + tid;
            int r = e >> 3, kq = (e & 7) << 2;
            av[q] = *(const float4*)&A[(size_t)(bm + r)*Kd + k0 + kq];
        }
        #pragma unroll
        for (int q = 0; q < 4; q++) {
            int e = q*256 + tid;
            int n = e & 63, j = e >> 6;
            bv0[q] = Bw[(size_t)(k0 + 2*j)*Nd + bn + n];
            bv1[q] = Bw[(size_t)(k0 + 2*j + 1)*Nd + bn + n];
        }
        __syncthreads();
        #pragma unroll
        for (int q = 0; q < 4; q++) {
            int e = q*256 + tid;
            int r = e >> 3, p = (e & 7)*2;
            unsigned h, l;
            split2(av[q].x, av[q].y, h, l); Ah[r][p]   = h; Al[r][p]   = l;
            split2(av[q].z, av[q].w, h, l); Ah[r][p+1] = h; Al[r][p+1] = l;
        }
        #pragma unroll
        for (int q = 0; q < 4; q++) {
            int e = q*256 + tid;
            int n = e & 63, j = e >> 6;
            unsigned h, l;
            split2(bv0[q], bv1[q], h, l);
            Bh[n][j] = h; Bl[n][j] = l;
        }
        __syncthreads();
        #pragma unroll
        for (int s = 0; s < 2; s++) {
            int p = s*8 + tig;
            unsigned ah[2][4], al[2][4];
            #pragma unroll
            for (int mi = 0; mi < 2; mi++) {
                int r = wm*32 + mi*16 + gid;
                ah[mi][0] = Ah[r][p];   ah[mi][1] = Ah[r+8][p];
                ah[mi][2] = Ah[r][p+4]; ah[mi][3] = Ah[r+8][p+4];
                al[mi][0] = Al[r][p];   al[mi][1] = Al[r+8][p];
                al[mi][2] = Al[r][p+4]; al[mi][3] = Al[r+8][p+4];
            }
            #pragma unroll
            for (int ni = 0; ni < 4; ni++) {
                int c = wn*32 + ni*8 + gid;
                unsigned bh0 = Bh[c][p], bh1 = Bh[c][p+4];
                unsigned bl0 = Bl[c][p], bl1 = Bl[c][p+4];
                #pragma unroll
                for (int mi = 0; mi < 2; mi++) {
                    MMA_BF16(acc[mi][ni], ah[mi][0],ah[mi][1],ah[mi][2],ah[mi][3], bh0,bh1);
                    MMA_BF16(acc[mi][ni], ah[mi][0],ah[mi][1],ah[mi][2],ah[mi][3], bl0,bl1);
                    MMA_BF16(acc[mi][ni], al[mi][0],al[mi][1],al[mi][2],al[mi][3], bh0,bh1);
                }
            }
        }
    }
    #pragma unroll
    for (int mi = 0; mi < 2; mi++) {
        int row = bm + wm*32 + mi*16 + gid;
        #pragma unroll
        for (int ni = 0; ni < 4; ni++) {
            int col = bn + wn*32 + ni*8 + tig*2;
            float bz0 = bias[col], bz1 = bias[col+1];
            float z0 = acc[mi][ni][0] + bz0;
            float z1 = acc[mi][ni][1] + bz1;
            float z2 = acc[mi][ni][2] + bz0;
            float z3 = acc[mi][ni][3] + bz1;
            if (RELU) {
                z0 = fmaxf(z0, 0.f); z1 = fmaxf(z1, 0.f);
                z2 = fmaxf(z2, 0.f); z3 = fmaxf(z3, 0.f);
            }
            *(float2*)&C[(size_t)row*Nd + col]     = make_float2(z0, z1);
            *(float2*)&C[(size_t)(row+8)*Nd + col] = make_float2(z2, z3);
        }
    }
}

// ---------------- host orchestration ----------------
template<int F, int BK>
static void run_conv(const float* xp, int ldx,
                     const float* w1, const float* b1,
                     const float* w2, const float* b2,
                     float* outp, int ldo) {
    sqnorm_k<F><<<NPT/256, 256>>>(xp, ldx);
    dist_k<F, BK><<<dim3(PTS/64, PTS/64, NG), 256>>>(xp, ldx);
    topk_k<<<NPT/8, 256>>>();
    precompute_k<F><<<(NPT*DIM)/256, 256>>>(xp, ldx, w1, b1);
    w2prep_k<<<8, 256>>>(w2);
    edgeconv_k<<<NPT/4, 128>>>(b2, outp, ldo);
}

extern "C" void kernel_launch(void* const* d_in, const int* in_sizes, int n_in,
                              void* d_out, int out_size) {
    const float* x    = (const float*)d_in[0];
    const float* c1w1 = (const float*)d_in[2];
    const float* c1b1 = (const float*)d_in[3];
    const float* c1w2 = (const float*)d_in[4];
    const float* c1b2 = (const float*)d_in[5];
    const float* c2w1 = (const float*)d_in[6];
    const float* c2b1 = (const float*)d_in[7];
    const float* c2w2 = (const float*)d_in[8];
    const float* c2b2 = (const float*)d_in[9];
    const float* c3w1 = (const float*)d_in[10];
    const float* c3b1 = (const float*)d_in[11];
    const float* c3w2 = (const float*)d_in[12];
    const float* c3b2 = (const float*)d_in[13];
    const float* lw   = (const float*)d_in[14];
    const float* lb   = (const float*)d_in[15];
    const float* hw1  = (const float*)d_in[16];
    const float* hb1  = (const float*)d_in[17];
    const float* hw2  = (const float*)d_in[18];
    const float* hb2  = (const float*)d_in[19];
    const float* hw3  = (const float*)d_in[20];
    const float* hb3  = (const float*)d_in[21];
    float* out = (float*)d_out;

    float *hcat, *big, *h1b, *h2b;
    cudaGetSymbolAddress((void**)&hcat, g_hcat);
    cudaGetSymbolAddress((void**)&big,  g_big);
    cudaGetSymbolAddress((void**)&h1b,  g_h1);
    cudaGetSymbolAddress((void**)&h2b,  g_h2);

    run_conv<14, 14>(x,         14,  c1w1, c1b1, c1w2, c1b2, hcat,       192);
    run_conv<64, 16>(hcat,      192, c2w1, c2b1, c2w2, c2b2, hcat + 64,  192);
    run_conv<64, 16>(hcat + 64, 192, c3w1, c3b1, c3w2, c3b2, hcat + 128, 192);

    hgemm_k<true ><<<dim3(16, 256), 256>>>(hcat, lw,  lb,  big, 192,  1024);
    hgemm_k<true ><<<dim3(4,  256), 256>>>(big,  hw1, hb1, h1b, 1024, 256);
    hgemm_k<true ><<<dim3(2,  256), 256>>>(h1b,  hw2, hb2, h2b, 256,  128);
    hgemm_k<false><<<dim3(1,  256), 256>>>(h2b,  hw3, hb3, out, 128,  64);
}